// round 10
// baseline (speedup 1.0000x reference)
#include <cuda_runtime.h>
#include <math.h>

#define TT 1024
#define DD 256
#define HD 256
#define LDA 72   // smem row stride (words): banks (8k+m) conflict-free for frag gather

// ---------------- scratch (device globals; no allocation allowed) ----------------
__device__ float g_K[TT*HD];
__device__ float g_Q[TT*HD];
__device__ float g_V[TT*HD];
__device__ float g_SKIP[TT*HD];
__device__ float g_S[TT*TT];
__device__ float g_ATT[TT*HD];
__device__ float g_H1[TT*HD];
__device__ float g_H2[TT*HD];
__device__ float g_H3[TT*HD];

__device__ unsigned      g_R0[33*1024];   // word-column staging of scan result R0[t+1]
__device__ unsigned      g_M[TT*32];      // mask: row t, bit u
__device__ unsigned char g_occ16[16*64];  // [row-tile(64)][col-chunk(16)] occupancy

__device__ float g_ksum[TT];
__device__ float g_qsum[TT];
__device__ float g_den[TT];

__device__ __forceinline__ float* buf(int id){
  switch(id){
    case 5: return g_ATT; case 6: return g_H1; case 7: return g_H2; case 8: return g_H3;
  }
  return g_ATT;
}

// ---------------- tf32 helpers ----------------
__device__ __forceinline__ unsigned f2tf32(float f){
  unsigned r; asm("cvt.rna.tf32.f32 %0, %1;" : "=r"(r) : "f"(f)); return r;
}
__device__ __forceinline__ void mma_tf32(float c[4], unsigned a0, unsigned a1,
                                         unsigned a2, unsigned a3,
                                         unsigned b0, unsigned b1){
  asm volatile("mma.sync.aligned.m16n8k8.row.col.f32.tf32.tf32.f32 "
               "{%0,%1,%2,%3}, {%4,%5,%6,%7}, {%8,%9}, {%0,%1,%2,%3};"
               : "+f"(c[0]), "+f"(c[1]), "+f"(c[2]), "+f"(c[3])
               : "r"(a0), "r"(a1), "r"(a2), "r"(a3), "r"(b0), "r"(b1));
}

// tf32 64x64 tile core: C[64,64] += A[row0:+64, :K] @ B[col0:+64, :K]^T
// 256 threads, warps in 4(row)x2(col), warp tile m16 x n32, fp32 accum.
// acc[s][r]: s = n-subtile (0..3, 8 cols each), r = c-frag reg.
template<int KDIM>
__device__ __forceinline__ void tf32_tile(const float* __restrict__ A,
                                          const float* __restrict__ B,
                                          int row0, int col0,
                                          unsigned* As, unsigned* Bs,
                                          float acc[4][4]){
  const int tid  = threadIdx.x;
  const int lane = tid & 31, wid = tid >> 5;
  const int m0 = (wid & 3) * 16, n0 = (wid >> 2) * 32;
  const int ar0 = tid >> 3, kc0 = (tid & 7) << 2;
  const int ar1 = ar0 + 32;
  const int kq = lane & 3, mq = lane >> 2;
  float4 a0 = *(const float4*)&A[(row0+ar0)*KDIM + kc0];
  float4 a1 = *(const float4*)&A[(row0+ar1)*KDIM + kc0];
  float4 b0 = *(const float4*)&B[(col0+ar0)*KDIM + kc0];
  float4 b1 = *(const float4*)&B[(col0+ar1)*KDIM + kc0];
  for(int k0 = 0; k0 < KDIM; k0 += 32){
    __syncthreads();
    As[(kc0+0)*LDA+ar0]=f2tf32(a0.x); As[(kc0+1)*LDA+ar0]=f2tf32(a0.y);
    As[(kc0+2)*LDA+ar0]=f2tf32(a0.z); As[(kc0+3)*LDA+ar0]=f2tf32(a0.w);
    As[(kc0+0)*LDA+ar1]=f2tf32(a1.x); As[(kc0+1)*LDA+ar1]=f2tf32(a1.y);
    As[(kc0+2)*LDA+ar1]=f2tf32(a1.z); As[(kc0+3)*LDA+ar1]=f2tf32(a1.w);
    Bs[(kc0+0)*LDA+ar0]=f2tf32(b0.x); Bs[(kc0+1)*LDA+ar0]=f2tf32(b0.y);
    Bs[(kc0+2)*LDA+ar0]=f2tf32(b0.z); Bs[(kc0+3)*LDA+ar0]=f2tf32(b0.w);
    Bs[(kc0+0)*LDA+ar1]=f2tf32(b1.x); Bs[(kc0+1)*LDA+ar1]=f2tf32(b1.y);
    Bs[(kc0+2)*LDA+ar1]=f2tf32(b1.z); Bs[(kc0+3)*LDA+ar1]=f2tf32(b1.w);
    __syncthreads();
    if(k0 + 32 < KDIM){
      a0 = *(const float4*)&A[(row0+ar0)*KDIM + k0 + 32 + kc0];
      a1 = *(const float4*)&A[(row0+ar1)*KDIM + k0 + 32 + kc0];
      b0 = *(const float4*)&B[(col0+ar0)*KDIM + k0 + 32 + kc0];
      b1 = *(const float4*)&B[(col0+ar1)*KDIM + k0 + 32 + kc0];
    }
    #pragma unroll
    for(int s8 = 0; s8 < 4; s8++){
      const int kk = s8*8 + kq;
      const unsigned fa0 = As[kk*LDA + m0 + mq];
      const unsigned fa1 = As[kk*LDA + m0 + mq + 8];
      const unsigned fa2 = As[(kk+4)*LDA + m0 + mq];
      const unsigned fa3 = As[(kk+4)*LDA + m0 + mq + 8];
      #pragma unroll
      for(int s = 0; s < 4; s++){
        const int nc = n0 + s*8 + mq;
        const unsigned fb0 = Bs[kk*LDA + nc];
        const unsigned fb1 = Bs[(kk+4)*LDA + nc];
        mma_tf32(acc[s], fa0, fa1, fa2, fa3, fb0, fb1);
      }
    }
  }
}

// ---------------- exact replica of jax.lax.associative_scan tree, on bitsets ----
__global__ void prep_scan(const int* __restrict__ start, const int* __restrict__ done){
  __shared__ unsigned E[2048];
  __shared__ unsigned R[2048];
  __shared__ unsigned char st[2048], dn[2048];
  const int n[11]   = {1025,512,256,128,64,32,16,8,4,2,1};
  const int off[11] = {0,1025,1537,1793,1921,1985,2017,2033,2041,2045,2047};
  const int w = blockIdx.x;        // word 0..32
  const int tid = threadIdx.x;     // 256

  for(int j = tid; j < 1025; j += 256){
    st[j] = (unsigned char)start[j];
    dn[j] = (unsigned char)done[j];
    E[j]  = ((j >> 5) == w) ? (1u << (j & 31)) : 0u;
  }
  __syncthreads();

  for(int k = 1; k < 11; k++){
    const int nk = n[k], ofk = off[k], ofp = off[k-1];
    for(int i = tid; i < nk; i += 256){
      const int a = ofp + 2*i, b = a + 1, o = ofk + i;
      unsigned v = 0u;
      if(st[b]) v  = E[a];
      if(dn[b]) v |= E[b];
      E[o] = v;
      st[o] = st[b]; dn[o] = dn[b];
    }
    __syncthreads();
  }

  if(tid == 0) R[2047] = E[2047];
  __syncthreads();
  for(int k = 9; k >= 0; k--){
    const int nk = n[k], ofk = off[k], ofc = off[k+1];
    for(int p = tid; p < nk; p += 256){
      unsigned v;
      if(p == 0){
        v = E[ofk];
      } else if(p & 1){
        v = R[ofc + (p>>1)];
      } else {
        const int b = ofk + p;
        v = 0u;
        if(st[b]) v  = R[ofc + (p>>1) - 1];
        if(dn[b]) v |= E[b];
      }
      R[ofk + p] = v;
    }
    __syncthreads();
  }

  for(int t = tid; t < 1024; t += 256) g_R0[w*1024 + t] = R[t + 1];
}

// ---------------- build final mask + tile occupancy ----------------
__global__ void prep_mask(){
  __shared__ unsigned Ms[64][32];
  const int rt = blockIdx.x;
  const int tid = threadIdx.x;      // 512
  for(int e = tid; e < 64*32; e += 512){
    const int r = e >> 5, w = e & 31;
    const int t = rt*64 + r;
    const unsigned lo = g_R0[w*1024 + t];
    const unsigned hi = g_R0[(w+1)*1024 + t];
    const unsigned m = (lo >> 1) | (hi << 31);
    Ms[r][w] = m;
    g_M[t*32 + w] = m;
  }
  __syncthreads();
  if(tid < 64){
    const int c = tid;
    const unsigned half = (c & 1) ? 0xFFFF0000u : 0x0000FFFFu;
    const int w = c >> 1;
    unsigned acc = 0u;
    #pragma unroll 8
    for(int r = 0; r < 64; r++) acc |= Ms[r][w];
    g_occ16[rt*64 + c] = (acc & half) ? 1 : 0;
  }
}

// ---------------- row sums of K and Q (float4 loads) ----------------
__global__ void rowsum_kernel(){
  const int row  = blockIdx.x*8 + (threadIdx.x >> 5);
  const int lane = threadIdx.x & 31;
  const float4* pk = (const float4*)&g_K[row*HD];
  const float4* pq = (const float4*)&g_Q[row*HD];
  float4 k0 = pk[lane], k1 = pk[lane+32];
  float4 q0 = pq[lane], q1 = pq[lane+32];
  float sk = k0.x+k0.y+k0.z+k0.w + k1.x+k1.y+k1.z+k1.w;
  float sq = q0.x+q0.y+q0.z+q0.w + q1.x+q1.y+q1.z+q1.w;
  #pragma unroll
  for(int o = 16; o; o >>= 1){
    sk += __shfl_down_sync(0xffffffffu, sk, o);
    sq += __shfl_down_sync(0xffffffffu, sq, o);
  }
  if(lane == 0){ g_ksum[row] = sk; g_qsum[row] = sq; }
}

// ---------------- denom[t] = max(qsum[t] * sum_u M[t][u]*ksum[u], 1e-5) --------
__global__ void den_kernel(){
  const int t    = blockIdx.x*8 + (threadIdx.x >> 5);
  const int lane = threadIdx.x & 31;
  unsigned m = g_M[t*32 + lane];
  float z = 0.f;
  while(m){
    const int b = __ffs(m) - 1;
    z += g_ksum[lane*32 + b];
    m &= m - 1;
  }
  #pragma unroll
  for(int o = 16; o; o >>= 1) z += __shfl_down_sync(0xffffffffu, z, o);
  if(lane == 0) g_den[t] = fmaxf(g_qsum[t] * z, 1e-5f);
}

// ---------------- fused projections (tf32): z in {K(elu),Q(elu),V,SKIP(+b)} ----
__global__ void proj_fused(const float* __restrict__ x,
                           const float* __restrict__ Wk, const float* __restrict__ Wq,
                           const float* __restrict__ Wv, const float* __restrict__ Ws,
                           const float* __restrict__ bskip){
  __shared__ unsigned As[32*LDA];
  __shared__ unsigned Bs[32*LDA];
  const int z = blockIdx.z;
  const float* W = (z==0) ? Wk : (z==1) ? Wq : (z==2) ? Wv : Ws;
  float* C = (z==0) ? g_K : (z==1) ? g_Q : (z==2) ? g_V : g_SKIP;
  const int row0 = blockIdx.y*64, col0 = blockIdx.x*64;
  float acc[4][4] = {};
  tf32_tile<DD>(x, W, row0, col0, As, Bs, acc);
  const int lane = threadIdx.x & 31, wid = threadIdx.x >> 5;
  const int m0 = (wid & 3) * 16, n0 = (wid >> 2) * 32;
  const int r1 = row0 + m0 + (lane >> 2);
  #pragma unroll
  for(int s = 0; s < 4; s++){
    const int c0 = col0 + n0 + s*8 + 2*(lane & 3);
    #pragma unroll
    for(int e = 0; e < 4; e++){
      const int row = r1 + (e >> 1)*8;
      const int col = c0 + (e & 1);
      float v = acc[s][e];
      if(z == 3) v += bskip[col];
      if(z < 2)  v = (v > 0.f) ? v : expm1f(v);
      C[row*HD + col] = v;
    }
  }
}

// ---------------- MLP GEMM (tf32): 64x64 tiles; buffers by id ----------------
__global__ void gemm_mlp(int a_id, const float* __restrict__ W,
                         const float* __restrict__ bias, int c_id,
                         int act, int add_skip){
  __shared__ unsigned As[32*LDA];
  __shared__ unsigned Bs[32*LDA];
  const float* A = buf(a_id);
  float* C = buf(c_id);
  const int row0 = blockIdx.y*64, col0 = blockIdx.x*64;
  float acc[4][4] = {};
  tf32_tile<HD>(A, W, row0, col0, As, Bs, acc);
  const int lane = threadIdx.x & 31, wid = threadIdx.x >> 5;
  const int m0 = (wid & 3) * 16, n0 = (wid >> 2) * 32;
  const int r1 = row0 + m0 + (lane >> 2);
  #pragma unroll
  for(int s = 0; s < 4; s++){
    const int c0 = col0 + n0 + s*8 + 2*(lane & 3);
    #pragma unroll
    for(int e = 0; e < 4; e++){
      const int row = r1 + (e >> 1)*8;
      const int col = c0 + (e & 1);
      float v = acc[s][e] + bias[col];
      if(act == 2){
        const float sp = (v > 20.f) ? v : log1pf(expf(v));
        v = v * tanhf(sp);
      }
      if(add_skip) v += g_SKIP[row*HD + col];
      C[row*HD + col] = v;
    }
  }
}

// ---------------- masked QK^T (tf32) with exact tree mask ----------------
__global__ void qk_kernel(){
  const int by = blockIdx.y, bx = blockIdx.x;
  if(bx > by) return;
  const unsigned occ4 = *(const unsigned*)&g_occ16[by*64 + bx*4];
  if(!occ4) return;
  __shared__ unsigned As[32*LDA];
  __shared__ unsigned Bs[32*LDA];
  const int r0 = by*64, c0 = bx*64;
  float acc[4][4] = {};
  tf32_tile<HD>(g_Q, g_K, r0, c0, As, Bs, acc);
  const int lane = threadIdx.x & 31, wid = threadIdx.x >> 5;
  const int m0 = (wid & 3) * 16, n0 = (wid >> 2) * 32;
  const int t1 = r0 + m0 + (lane >> 2);
  #pragma unroll
  for(int s = 0; s < 4; s++){
    const int u0 = c0 + n0 + s*8 + 2*(lane & 3);
    #pragma unroll
    for(int e = 0; e < 4; e++){
      const int t = t1 + (e >> 1)*8;
      const int u = u0 + (e & 1);
      const unsigned mw = g_M[t*32 + (u>>5)];
      g_S[t*TT + u] = ((mw >> (u&31)) & 1u) ? acc[s][e] : 0.f;
    }
  }
}

// ---------------- out = (S @ V) / den  (fp32, sparse chunks) ----------------
__global__ void sv_kernel(){
  const int by = blockIdx.y, bx = blockIdx.x;
  const int r0 = by*64, col0 = bx*64;
  __shared__ __align__(16) float As[16][68];
  __shared__ __align__(16) float Bs[16][64];
  const int tid = threadIdx.x;
  const int tx = tid & 15, ty = tid >> 4;
  const int r  = tid >> 2, c4 = (tid & 3) << 2;
  float acc[4][4] = {};
  for(int u0 = 0; u0 < TT && u0 <= r0 + 63; u0 += 16){
    if(!g_occ16[by*64 + (u0>>4)]) continue;
    float4 av = *(const float4*)&g_S[(r0 + r)*TT + u0 + c4];
    int vr = tid >> 4, vc4 = (tid & 15) << 2;
    float4 bv = *(const float4*)&g_V[(u0 + vr)*HD + col0 + vc4];
    __syncthreads();
    As[c4+0][r]=av.x; As[c4+1][r]=av.y; As[c4+2][r]=av.z; As[c4+3][r]=av.w;
    *(float4*)&Bs[vr][vc4] = bv;
    __syncthreads();
    #pragma unroll
    for(int k=0;k<16;k++){
      const float4 a4 = *(const float4*)&As[k][ty*4];
      const float4 b4 = *(const float4*)&Bs[k][tx*4];
      const float av2[4] = {a4.x,a4.y,a4.z,a4.w};
      #pragma unroll
      for(int i=0;i<4;i++){
        acc[i][0] += av2[i]*b4.x; acc[i][1] += av2[i]*b4.y;
        acc[i][2] += av2[i]*b4.z; acc[i][3] += av2[i]*b4.w;
      }
    }
  }
  #pragma unroll
  for(int i=0;i<4;i++){
    const int t = r0 + ty*4 + i;
    const float inv = 1.f / g_den[t];
    #pragma unroll
    for(int j=0;j<4;j++)
      g_ATT[t*HD + col0 + tx*4 + j] = acc[i][j] * inv;
  }
}

// ---------------- LayerNorm over H=256 per row ----------------
__global__ void ln_kernel(const float* __restrict__ w, const float* __restrict__ b,
                          float* __restrict__ out){
  const int row = blockIdx.x, t = threadIdx.x;
  float v = g_H3[row*HD + t];
  __shared__ float red[8];
  __shared__ float sh_mu, sh_var;
  float s = v;
  #pragma unroll
  for(int o=16;o;o>>=1) s += __shfl_down_sync(0xffffffffu, s, o);
  if((t & 31) == 0) red[t >> 5] = s;
  __syncthreads();
  if(t == 0){ float tot = 0.f; for(int i=0;i<8;i++) tot += red[i]; sh_mu = tot / (float)HD; }
  __syncthreads();
  float d = v - sh_mu;
  float s2 = d*d;
  #pragma unroll
  for(int o=16;o;o>>=1) s2 += __shfl_down_sync(0xffffffffu, s2, o);
  if((t & 31) == 0) red[t >> 5] = s2;
  __syncthreads();
  if(t == 0){ float tot = 0.f; for(int i=0;i<8;i++) tot += red[i]; sh_var = tot / (float)HD; }
  __syncthreads();
  out[row*HD + t] = d * rsqrtf(sh_var + 1e-5f) * w[t] + b[t];
}

// ---------------- launch ----------------
extern "C" void kernel_launch(void* const* d_in, const int* in_sizes, int n_in,
                              void* d_out, int out_size){
  const float* x     = (const float*)d_in[0];
  const int*   start = (const int*)  d_in[3];
  const int*   done  = (const int*)  d_in[4];
  const float* Wk    = (const float*)d_in[5];
  const float* Wq    = (const float*)d_in[6];
  const float* Wv    = (const float*)d_in[7];
  const float* Wskip = (const float*)d_in[8];
  const float* bskip = (const float*)d_in[9];
  const float* W1    = (const float*)d_in[10];
  const float* b1    = (const float*)d_in[11];
  const float* W2    = (const float*)d_in[12];
  const float* b2    = (const float*)d_in[13];
  const float* W3    = (const float*)d_in[14];
  const float* b3    = (const float*)d_in[15];
  const float* lnw   = (const float*)d_in[16];
  const float* lnb   = (const float*)d_in[17];
  float* out = (float*)d_out;

  prep_scan<<<33, 256>>>(start, done);
  prep_mask<<<16, 512>>>();

  proj_fused<<<dim3(HD/64, TT/64, 4), 256>>>(x, Wk, Wq, Wv, Wskip, bskip);

  rowsum_kernel<<<TT/8, 256>>>();
  den_kernel<<<TT/8, 256>>>();

  qk_kernel<<<dim3(TT/64, TT/64), 256>>>();
  sv_kernel<<<dim3(HD/64, TT/64), 256>>>();

  gemm_mlp<<<dim3(HD/64, TT/64), 256>>>(5, W1, b1, 6, 2, 0);   // ATT -> H1 (mish)
  gemm_mlp<<<dim3(HD/64, TT/64), 256>>>(6, W2, b2, 7, 2, 0);   // H1  -> H2 (mish)
  gemm_mlp<<<dim3(HD/64, TT/64), 256>>>(7, W3, b3, 8, 0, 1);   // H2  -> H3 (+skip)

  ln_kernel<<<TT, 256>>>(lnw, lnb, out);
}

// round 11
// speedup vs baseline: 1.4027x; 1.4027x over previous
#include <cuda_runtime.h>
#include <math.h>

#define TT 1024
#define DD 256
#define HD 256
#define TLD 36          // smem row stride (words) for tf32 tiles
#define ABUF (64*TLD)   // one tile buffer (words)

// ---------------- scratch (device globals; no allocation allowed) ----------------
__device__ float g_K[TT*HD];
__device__ float g_Q[TT*HD];
__device__ float g_V[TT*HD];
__device__ float g_SKIP[TT*HD];
__device__ float g_S[TT*TT];
__device__ float g_ATT[TT*HD];
__device__ float g_H1[TT*HD];
__device__ float g_H2[TT*HD];
__device__ float g_H3[TT*HD];

__device__ unsigned      g_R0[33*1024];
__device__ unsigned      g_M[TT*32];      // mask: row t, bit u
__device__ unsigned char g_occ16[16*64];  // [row-tile(64)][col-chunk(16)] occupancy

__device__ float g_ksum[TT];
__device__ float g_qsum[TT];

__device__ __forceinline__ float* buf(int id){
  switch(id){
    case 5: return g_ATT; case 6: return g_H1; case 7: return g_H2; case 8: return g_H3;
  }
  return g_ATT;
}

// ---------------- tf32 helpers ----------------
__device__ __forceinline__ unsigned f2tf32(float f){
  unsigned r; asm("cvt.rna.tf32.f32 %0, %1;" : "=r"(r) : "f"(f)); return r;
}
__device__ __forceinline__ void mma_tf32(float c[4], unsigned a0, unsigned a1,
                                         unsigned a2, unsigned a3,
                                         unsigned b0, unsigned b1){
  asm volatile("mma.sync.aligned.m16n8k8.row.col.f32.tf32.tf32.f32 "
               "{%0,%1,%2,%3}, {%4,%5,%6,%7}, {%8,%9}, {%0,%1,%2,%3};"
               : "+f"(c[0]), "+f"(c[1]), "+f"(c[2]), "+f"(c[3])
               : "r"(a0), "r"(a1), "r"(a2), "r"(a3), "r"(b0), "r"(b1));
}
__device__ __forceinline__ void st_tf32(unsigned* base, int row, int kc, float4 v){
  uint4 u; u.x = f2tf32(v.x); u.y = f2tf32(v.y); u.z = f2tf32(v.z); u.w = f2tf32(v.w);
  *(uint4*)&base[row*TLD + kc] = u;
}

// tf32 64x64 tile core: C[64,64] += A[row0:+64, :K] @ B[col0:+64, :K]^T
// 256 threads, warps 4(m)x2(n), warp tile m16 x n32, fp32 accum.
// Double-buffered m-major/n-major smem, STS.128 loader, conflict-free gather.
template<int KDIM>
__device__ __forceinline__ void tf32_tile(const float* __restrict__ A,
                                          const float* __restrict__ B,
                                          int row0, int col0,
                                          unsigned* As, unsigned* Bs,
                                          float acc[4][4]){
  const int tid  = threadIdx.x;
  const int lane = tid & 31, wid = tid >> 5;
  const int m0 = (wid & 3) * 16, n0 = (wid >> 2) * 32;
  const int mq = lane >> 2, kq = lane & 3;
  const int ar0 = tid >> 3, kc = (tid & 7) << 2, ar1 = ar0 + 32;
  const float* pa0 = &A[(row0+ar0)*KDIM + kc];
  const float* pa1 = &A[(row0+ar1)*KDIM + kc];
  const float* pb0 = &B[(col0+ar0)*KDIM + kc];
  const float* pb1 = &B[(col0+ar1)*KDIM + kc];

  // prologue: load + store chunk 0 into buffer 0
  {
    float4 a0 = *(const float4*)pa0;
    float4 a1 = *(const float4*)pa1;
    float4 b0 = *(const float4*)pb0;
    float4 b1 = *(const float4*)pb1;
    st_tf32(As, ar0, kc, a0); st_tf32(As, ar1, kc, a1);
    st_tf32(Bs, ar0, kc, b0); st_tf32(Bs, ar1, kc, b1);
  }
  const int NC = KDIM / 32;
  int cur = 0;
  for(int c = 0; c < NC; c++){
    __syncthreads();
    float4 na0, na1, nb0, nb1;
    if(c + 1 < NC){
      na0 = *(const float4*)(pa0 + (c+1)*32);
      na1 = *(const float4*)(pa1 + (c+1)*32);
      nb0 = *(const float4*)(pb0 + (c+1)*32);
      nb1 = *(const float4*)(pb1 + (c+1)*32);
    }
    const unsigned* Ab = As + cur*ABUF;
    const unsigned* Bb = Bs + cur*ABUF;
    #pragma unroll
    for(int s8 = 0; s8 < 4; s8++){
      const int kk = s8*8 + kq;
      const unsigned fa0 = Ab[(m0+mq  )*TLD + kk];
      const unsigned fa1 = Ab[(m0+mq+8)*TLD + kk];
      const unsigned fa2 = Ab[(m0+mq  )*TLD + kk + 4];
      const unsigned fa3 = Ab[(m0+mq+8)*TLD + kk + 4];
      #pragma unroll
      for(int s = 0; s < 4; s++){
        const int nc2 = n0 + s*8 + mq;
        const unsigned fb0 = Bb[nc2*TLD + kk];
        const unsigned fb1 = Bb[nc2*TLD + kk + 4];
        mma_tf32(acc[s], fa0, fa1, fa2, fa3, fb0, fb1);
      }
    }
    if(c + 1 < NC){
      unsigned* An = As + (cur^1)*ABUF;
      unsigned* Bn = Bs + (cur^1)*ABUF;
      st_tf32(An, ar0, kc, na0); st_tf32(An, ar1, kc, na1);
      st_tf32(Bn, ar0, kc, nb0); st_tf32(Bn, ar1, kc, nb1);
    }
    cur ^= 1;
  }
}

// ---------------- exact replica of jax.lax.associative_scan tree, on bitsets ----
__global__ void prep_scan(const int* __restrict__ start, const int* __restrict__ done){
  __shared__ unsigned E[2048];
  __shared__ unsigned R[2048];
  __shared__ unsigned char st[2048], dn[2048];
  const int n[11]   = {1025,512,256,128,64,32,16,8,4,2,1};
  const int off[11] = {0,1025,1537,1793,1921,1985,2017,2033,2041,2045,2047};
  const int w = blockIdx.x;        // word 0..32
  const int tid = threadIdx.x;     // 256

  for(int j = tid; j < 1025; j += 256){
    st[j] = (unsigned char)start[j];
    dn[j] = (unsigned char)done[j];
    E[j]  = ((j >> 5) == w) ? (1u << (j & 31)) : 0u;
  }
  __syncthreads();

  for(int k = 1; k < 11; k++){
    const int nk = n[k], ofk = off[k], ofp = off[k-1];
    for(int i = tid; i < nk; i += 256){
      const int a = ofp + 2*i, b = a + 1, o = ofk + i;
      unsigned v = 0u;
      if(st[b]) v  = E[a];
      if(dn[b]) v |= E[b];
      E[o] = v;
      st[o] = st[b]; dn[o] = dn[b];
    }
    __syncthreads();
  }

  if(tid == 0) R[2047] = E[2047];
  __syncthreads();
  for(int k = 9; k >= 0; k--){
    const int nk = n[k], ofk = off[k], ofc = off[k+1];
    for(int p = tid; p < nk; p += 256){
      unsigned v;
      if(p == 0){
        v = E[ofk];
      } else if(p & 1){
        v = R[ofc + (p>>1)];
      } else {
        const int b = ofk + p;
        v = 0u;
        if(st[b]) v  = R[ofc + (p>>1) - 1];
        if(dn[b]) v |= E[b];
      }
      R[ofk + p] = v;
    }
    __syncthreads();
  }

  for(int t = tid; t < 1024; t += 256) g_R0[w*1024 + t] = R[t + 1];
}

// ---------------- build final mask + tile occupancy + zero row-sums ------------
__global__ void prep_mask(){
  __shared__ unsigned Ms[64][32];
  const int rt = blockIdx.x;
  const int tid = threadIdx.x;      // 512
  for(int e = tid; e < 64*32; e += 512){
    const int r = e >> 5, w = e & 31;
    const int t = rt*64 + r;
    const unsigned lo = g_R0[w*1024 + t];
    const unsigned hi = g_R0[(w+1)*1024 + t];
    const unsigned m = (lo >> 1) | (hi << 31);
    Ms[r][w] = m;
    g_M[t*32 + w] = m;
  }
  __syncthreads();
  if(tid < 64){
    const int c = tid;
    const unsigned half = (c & 1) ? 0xFFFF0000u : 0x0000FFFFu;
    const int w = c >> 1;
    unsigned acc = 0u;
    #pragma unroll 8
    for(int r = 0; r < 64; r++) acc |= Ms[r][w];
    g_occ16[rt*64 + c] = (acc & half) ? 1 : 0;
    g_ksum[rt*64 + c] = 0.f;       // zero for proj epilogue atomics
    g_qsum[rt*64 + c] = 0.f;
  }
}

// ---------------- fused projections (tf32) + K/Q row-sum epilogue --------------
__global__ void proj_fused(const float* __restrict__ x,
                           const float* __restrict__ Wk, const float* __restrict__ Wq,
                           const float* __restrict__ Wv, const float* __restrict__ Ws,
                           const float* __restrict__ bskip){
  __shared__ unsigned As[2*ABUF];
  __shared__ unsigned Bs[2*ABUF];
  const int z = blockIdx.z;
  const float* W = (z==0) ? Wk : (z==1) ? Wq : (z==2) ? Wv : Ws;
  float* C = (z==0) ? g_K : (z==1) ? g_Q : (z==2) ? g_V : g_SKIP;
  const int row0 = blockIdx.y*64, col0 = blockIdx.x*64;
  float acc[4][4] = {};
  tf32_tile<DD>(x, W, row0, col0, As, Bs, acc);
  const int lane = threadIdx.x & 31, wid = threadIdx.x >> 5;
  const int m0 = (wid & 3) * 16, n0 = (wid >> 2) * 32;
  const int r1 = row0 + m0 + (lane >> 2);
  float rs[2] = {0.f, 0.f};     // row sums for rows r1, r1+8 (this warp's 32 cols)
  #pragma unroll
  for(int s = 0; s < 4; s++){
    const int c0 = col0 + n0 + s*8 + 2*(lane & 3);
    #pragma unroll
    for(int e = 0; e < 4; e++){
      const int row = r1 + (e >> 1)*8;
      const int col = c0 + (e & 1);
      float v = acc[s][e];
      if(z == 3) v += bskip[col];
      if(z < 2)  v = (v > 0.f) ? v : expm1f(v);
      rs[e >> 1] += v;
      C[row*HD + col] = v;
    }
  }
  if(z < 2){
    float* sum = (z == 0) ? g_ksum : g_qsum;
    #pragma unroll
    for(int o = 1; o <= 2; o <<= 1){
      rs[0] += __shfl_xor_sync(0xffffffffu, rs[0], o);
      rs[1] += __shfl_xor_sync(0xffffffffu, rs[1], o);
    }
    if((lane & 3) == 0){
      atomicAdd(&sum[r1],     rs[0]);
      atomicAdd(&sum[r1 + 8], rs[1]);
    }
  }
}

// ---------------- MLP GEMM (tf32): 64x64 tiles; buffers by id ----------------
__global__ void gemm_mlp(int a_id, const float* __restrict__ W,
                         const float* __restrict__ bias, int c_id,
                         int act, int add_skip){
  __shared__ unsigned As[2*ABUF];
  __shared__ unsigned Bs[2*ABUF];
  const float* A = buf(a_id);
  float* C = buf(c_id);
  const int row0 = blockIdx.y*64, col0 = blockIdx.x*64;
  float acc[4][4] = {};
  tf32_tile<HD>(A, W, row0, col0, As, Bs, acc);
  const int lane = threadIdx.x & 31, wid = threadIdx.x >> 5;
  const int m0 = (wid & 3) * 16, n0 = (wid >> 2) * 32;
  const int r1 = row0 + m0 + (lane >> 2);
  #pragma unroll
  for(int s = 0; s < 4; s++){
    const int c0 = col0 + n0 + s*8 + 2*(lane & 3);
    #pragma unroll
    for(int e = 0; e < 4; e++){
      const int row = r1 + (e >> 1)*8;
      const int col = c0 + (e & 1);
      float v = acc[s][e] + bias[col];
      if(act == 2){
        const float sp = (v > 20.f) ? v : log1pf(expf(v));
        v = v * tanhf(sp);
      }
      if(add_skip) v += g_SKIP[row*HD + col];
      C[row*HD + col] = v;
    }
  }
}

// ---------------- masked QK^T (tf32) with exact tree mask ----------------
__global__ void qk_kernel(){
  const int by = blockIdx.y, bx = blockIdx.x;
  if(bx > by) return;
  const unsigned occ4 = *(const unsigned*)&g_occ16[by*64 + bx*4];
  if(!occ4) return;
  __shared__ unsigned As[2*ABUF];
  __shared__ unsigned Bs[2*ABUF];
  const int r0 = by*64, c0 = bx*64;
  float acc[4][4] = {};
  tf32_tile<HD>(g_Q, g_K, r0, c0, As, Bs, acc);
  const int lane = threadIdx.x & 31, wid = threadIdx.x >> 5;
  const int m0 = (wid & 3) * 16, n0 = (wid >> 2) * 32;
  const int t1 = r0 + m0 + (lane >> 2);
  #pragma unroll
  for(int s = 0; s < 4; s++){
    const int u0 = c0 + n0 + s*8 + 2*(lane & 3);
    #pragma unroll
    for(int e = 0; e < 4; e++){
      const int t = t1 + (e >> 1)*8;
      const int u = u0 + (e & 1);
      const unsigned mw = g_M[t*32 + (u>>5)];
      g_S[t*TT + u] = ((mw >> (u&31)) & 1u) ? acc[s][e] : 0.f;
    }
  }
}

// ---------------- out = (S @ V) / den  (fp32, sparse chunks; den inline) -------
__global__ void sv_kernel(){
  const int by = blockIdx.y, bx = blockIdx.x;
  const int r0 = by*64, col0 = bx*64;
  __shared__ __align__(16) float As[16][68];
  __shared__ __align__(16) float Bs[16][64];
  __shared__ float den_s[64];
  const int tid = threadIdx.x;
  const int lane = tid & 31, wid = tid >> 5;
  // denom for this row-tile: 8 warps x 8 passes, lane-per-mask-word
  #pragma unroll
  for(int p = 0; p < 8; p++){
    const int row = r0 + p*8 + wid;
    unsigned m = g_M[row*32 + lane];
    float zz = 0.f;
    while(m){
      const int b = __ffs(m) - 1;
      zz += g_ksum[lane*32 + b];
      m &= m - 1;
    }
    #pragma unroll
    for(int o = 16; o; o >>= 1) zz += __shfl_down_sync(0xffffffffu, zz, o);
    if(lane == 0) den_s[p*8 + wid] = fmaxf(g_qsum[row] * zz, 1e-5f);
  }
  const int tx = tid & 15, ty = tid >> 4;
  const int r  = tid >> 2, c4 = (tid & 3) << 2;
  float acc[4][4] = {};
  for(int u0 = 0; u0 < TT && u0 <= r0 + 63; u0 += 16){
    if(!g_occ16[by*64 + (u0>>4)]) continue;
    float4 av = *(const float4*)&g_S[(r0 + r)*TT + u0 + c4];
    int vr = tid >> 4, vc4 = (tid & 15) << 2;
    float4 bv = *(const float4*)&g_V[(u0 + vr)*HD + col0 + vc4];
    __syncthreads();
    As[c4+0][r]=av.x; As[c4+1][r]=av.y; As[c4+2][r]=av.z; As[c4+3][r]=av.w;
    *(float4*)&Bs[vr][vc4] = bv;
    __syncthreads();
    #pragma unroll
    for(int k=0;k<16;k++){
      const float4 a4 = *(const float4*)&As[k][ty*4];
      const float4 b4 = *(const float4*)&Bs[k][tx*4];
      const float av2[4] = {a4.x,a4.y,a4.z,a4.w};
      #pragma unroll
      for(int i=0;i<4;i++){
        acc[i][0] += av2[i]*b4.x; acc[i][1] += av2[i]*b4.y;
        acc[i][2] += av2[i]*b4.z; acc[i][3] += av2[i]*b4.w;
      }
    }
  }
  __syncthreads();
  #pragma unroll
  for(int i=0;i<4;i++){
    const int rr = ty*4 + i;
    const float inv = 1.f / den_s[rr];
    #pragma unroll
    for(int j=0;j<4;j++)
      g_ATT[(r0 + rr)*HD + col0 + tx*4 + j] = acc[i][j] * inv;
  }
}

// ---------------- LayerNorm over H=256 per row ----------------
__global__ void ln_kernel(const float* __restrict__ w, const float* __restrict__ b,
                          float* __restrict__ out){
  const int row = blockIdx.x, t = threadIdx.x;
  float v = g_H3[row*HD + t];
  __shared__ float red[8];
  __shared__ float sh_mu, sh_var;
  float s = v;
  #pragma unroll
  for(int o=16;o;o>>=1) s += __shfl_down_sync(0xffffffffu, s, o);
  if((t & 31) == 0) red[t >> 5] = s;
  __syncthreads();
  if(t == 0){ float tot = 0.f; for(int i=0;i<8;i++) tot += red[i]; sh_mu = tot / (float)HD; }
  __syncthreads();
  float d = v - sh_mu;
  float s2 = d*d;
  #pragma unroll
  for(int o=16;o;o>>=1) s2 += __shfl_down_sync(0xffffffffu, s2, o);
  if((t & 31) == 0) red[t >> 5] = s2;
  __syncthreads();
  if(t == 0){ float tot = 0.f; for(int i=0;i<8;i++) tot += red[i]; sh_var = tot / (float)HD; }
  __syncthreads();
  out[row*HD + t] = d * rsqrtf(sh_var + 1e-5f) * w[t] + b[t];
}

// ---------------- launch ----------------
extern "C" void kernel_launch(void* const* d_in, const int* in_sizes, int n_in,
                              void* d_out, int out_size){
  const float* x     = (const float*)d_in[0];
  const int*   start = (const int*)  d_in[3];
  const int*   done  = (const int*)  d_in[4];
  const float* Wk    = (const float*)d_in[5];
  const float* Wq    = (const float*)d_in[6];
  const float* Wv    = (const float*)d_in[7];
  const float* Wskip = (const float*)d_in[8];
  const float* bskip = (const float*)d_in[9];
  const float* W1    = (const float*)d_in[10];
  const float* b1    = (const float*)d_in[11];
  const float* W2    = (const float*)d_in[12];
  const float* b2    = (const float*)d_in[13];
  const float* W3    = (const float*)d_in[14];
  const float* b3    = (const float*)d_in[15];
  const float* lnw   = (const float*)d_in[16];
  const float* lnb   = (const float*)d_in[17];
  float* out = (float*)d_out;

  prep_scan<<<33, 256>>>(start, done);
  prep_mask<<<16, 512>>>();

  proj_fused<<<dim3(HD/64, TT/64, 4), 256>>>(x, Wk, Wq, Wv, Wskip, bskip);

  qk_kernel<<<dim3(TT/64, TT/64), 256>>>();
  sv_kernel<<<dim3(HD/64, TT/64), 256>>>();

  gemm_mlp<<<dim3(HD/64, TT/64), 256>>>(5, W1, b1, 6, 2, 0);   // ATT -> H1 (mish)
  gemm_mlp<<<dim3(HD/64, TT/64), 256>>>(6, W2, b2, 7, 2, 0);   // H1  -> H2 (mish)
  gemm_mlp<<<dim3(HD/64, TT/64), 256>>>(7, W3, b3, 8, 0, 1);   // H2  -> H3 (+skip)

  ln_kernel<<<TT, 256>>>(lnw, lnb, out);
}

// round 14
// speedup vs baseline: 1.4092x; 1.0046x over previous
#include <cuda_runtime.h>
#include <math.h>

#define TT 1024
#define DD 256
#define HD 256
#define TLD 36              // smem row stride (words) for tf32 tiles
#define STAGE (64*TLD)      // words per matrix per stage (2304)
#define NSTAGE 4
#define SMEMB (2*NSTAGE*STAGE*4)   // 73728 bytes dynamic smem

// ---------------- scratch (device globals; no allocation allowed) ----------------
__device__ float g_K[TT*HD];
__device__ float g_Q[TT*HD];
__device__ float g_V[TT*HD];
__device__ float g_SKIP[TT*HD];
__device__ float g_S[TT*TT];
__device__ float g_ATT[TT*HD];
__device__ float g_H1[TT*HD];
__device__ float g_H2[TT*HD];
__device__ float g_H3[TT*HD];

__device__ unsigned      g_R0[33*1024];
__device__ unsigned      g_M[TT*32];      // mask: row t, bit u
__device__ unsigned char g_occ16[16*64];  // [row-tile(64)][col-chunk(16)] occupancy

__device__ float g_ksum[TT];
__device__ float g_qsum[TT];

__device__ __forceinline__ float* buf(int id){
  switch(id){
    case 5: return g_ATT; case 6: return g_H1; case 7: return g_H2; case 8: return g_H3;
  }
  return g_ATT;
}

// ---------------- tf32 / cp.async helpers ----------------
__device__ __forceinline__ unsigned f2tf32(float f){
  unsigned r; asm("cvt.rna.tf32.f32 %0, %1;" : "=r"(r) : "f"(f)); return r;
}
__device__ __forceinline__ void mma_tf32(float c[4], unsigned a0, unsigned a1,
                                         unsigned a2, unsigned a3,
                                         unsigned b0, unsigned b1){
  asm volatile("mma.sync.aligned.m16n8k8.row.col.f32.tf32.tf32.f32 "
               "{%0,%1,%2,%3}, {%4,%5,%6,%7}, {%8,%9}, {%0,%1,%2,%3};"
               : "+f"(c[0]), "+f"(c[1]), "+f"(c[2]), "+f"(c[3])
               : "r"(a0), "r"(a1), "r"(a2), "r"(a3), "r"(b0), "r"(b1));
}
__device__ __forceinline__ unsigned smem_u32(const void* p){
  return (unsigned)__cvta_generic_to_shared(p);
}
#define CPA16(dst, src) asm volatile("cp.async.cg.shared.global [%0], [%1], 16;" :: "r"(dst), "l"(src) : "memory")
#define CPCOMMIT()      asm volatile("cp.async.commit_group;" ::: "memory")
#define CPWAIT(n)       asm volatile("cp.async.wait_group %0;" :: "n"(n) : "memory")

// tf32 64x64 tile core: C += A[row0:+64,:K] @ B[col0:+64,:K]^T
// 256 threads, warps 4(m)x2(n), warp tile m16 x n32, fp32 accum.
// 4-stage cp.async ring in dynamic smem; tf32 cvt at fragment load.
template<int KDIM>
__device__ __forceinline__ void tf32_tile(const float* __restrict__ A,
                                          const float* __restrict__ B,
                                          int row0, int col0,
                                          float* __restrict__ smem,
                                          float acc[4][4]){
  float* As = smem;
  float* Bs = smem + NSTAGE*STAGE;
  const int tid = threadIdx.x, lane = tid & 31, wid = tid >> 5;
  const int m0 = (wid & 3) * 16, n0 = (wid >> 2) * 32;
  const int mq = lane >> 2, kq = lane & 3;
  const int ar0 = tid >> 3, kc = (tid & 7) << 2, ar1 = ar0 + 32;
  const float* pa0 = &A[(row0+ar0)*KDIM + kc];
  const float* pa1 = &A[(row0+ar1)*KDIM + kc];
  const float* pb0 = &B[(col0+ar0)*KDIM + kc];
  const float* pb1 = &B[(col0+ar1)*KDIM + kc];
  const unsigned da0 = smem_u32(&As[ar0*TLD + kc]);
  const unsigned da1 = smem_u32(&As[ar1*TLD + kc]);
  const unsigned db0 = smem_u32(&Bs[ar0*TLD + kc]);
  const unsigned db1 = smem_u32(&Bs[ar1*TLD + kc]);
  const int NC = KDIM / 32;

  #pragma unroll
  for(int s = 0; s < NSTAGE-1; s++){
    const unsigned off = (s & (NSTAGE-1)) * STAGE * 4;
    CPA16(da0 + off, pa0 + s*32); CPA16(da1 + off, pa1 + s*32);
    CPA16(db0 + off, pb0 + s*32); CPA16(db1 + off, pb1 + s*32);
    CPCOMMIT();
  }
  for(int c = 0; c < NC; c++){
    CPWAIT(NSTAGE-2);
    __syncthreads();
    const float* Ab = &As[(c & (NSTAGE-1)) * STAGE];
    const float* Bb = &Bs[(c & (NSTAGE-1)) * STAGE];
    #pragma unroll
    for(int s8 = 0; s8 < 4; s8++){
      const int kk = s8*8 + kq;
      const unsigned fa0 = f2tf32(Ab[(m0+mq  )*TLD + kk]);
      const unsigned fa1 = f2tf32(Ab[(m0+mq+8)*TLD + kk]);
      const unsigned fa2 = f2tf32(Ab[(m0+mq  )*TLD + kk + 4]);
      const unsigned fa3 = f2tf32(Ab[(m0+mq+8)*TLD + kk + 4]);
      #pragma unroll
      for(int s = 0; s < 4; s++){
        const int nc2 = n0 + s*8 + mq;
        const unsigned fb0 = f2tf32(Bb[nc2*TLD + kk]);
        const unsigned fb1 = f2tf32(Bb[nc2*TLD + kk + 4]);
        mma_tf32(acc[s], fa0, fa1, fa2, fa3, fb0, fb1);
      }
    }
    __syncthreads();
    const int nx = c + NSTAGE - 1;
    if(nx < NC){
      const unsigned off = (nx & (NSTAGE-1)) * STAGE * 4;
      CPA16(da0 + off, pa0 + nx*32); CPA16(da1 + off, pa1 + nx*32);
      CPA16(db0 + off, pb0 + nx*32); CPA16(db1 + off, pb1 + nx*32);
      CPCOMMIT();
    }
  }
}

// ---------------- exact replica of jax.lax.associative_scan tree, on bitsets ----
__global__ void prep_scan(const int* __restrict__ start, const int* __restrict__ done){
  __shared__ unsigned E[2048];
  __shared__ unsigned R[2048];
  __shared__ unsigned char st[2048], dn[2048];
  const int n[11]   = {1025,512,256,128,64,32,16,8,4,2,1};
  const int off[11] = {0,1025,1537,1793,1921,1985,2017,2033,2041,2045,2047};
  const int w = blockIdx.x;
  const int tid = threadIdx.x;

  for(int j = tid; j < 1025; j += 256){
    st[j] = (unsigned char)start[j];
    dn[j] = (unsigned char)done[j];
    E[j]  = ((j >> 5) == w) ? (1u << (j & 31)) : 0u;
  }
  __syncthreads();

  for(int k = 1; k < 11; k++){
    const int nk = n[k], ofk = off[k], ofp = off[k-1];
    for(int i = tid; i < nk; i += 256){
      const int a = ofp + 2*i, b = a + 1, o = ofk + i;
      unsigned v = 0u;
      if(st[b]) v  = E[a];
      if(dn[b]) v |= E[b];
      E[o] = v;
      st[o] = st[b]; dn[o] = dn[b];
    }
    __syncthreads();
  }

  if(tid == 0) R[2047] = E[2047];
  __syncthreads();
  for(int k = 9; k >= 0; k--){
    const int nk = n[k], ofk = off[k], ofc = off[k+1];
    for(int p = tid; p < nk; p += 256){
      unsigned v;
      if(p == 0){
        v = E[ofk];
      } else if(p & 1){
        v = R[ofc + (p>>1)];
      } else {
        const int b = ofk + p;
        v = 0u;
        if(st[b]) v  = R[ofc + (p>>1) - 1];
        if(dn[b]) v |= E[b];
      }
      R[ofk + p] = v;
    }
    __syncthreads();
  }

  for(int t = tid; t < 1024; t += 256) g_R0[w*1024 + t] = R[t + 1];
}

// ---------------- build final mask + tile occupancy + zero row-sums ------------
__global__ void prep_mask(){
  __shared__ unsigned Ms[64][32];
  const int rt = blockIdx.x;
  const int tid = threadIdx.x;      // 512
  for(int e = tid; e < 64*32; e += 512){
    const int r = e >> 5, w = e & 31;
    const int t = rt*64 + r;
    const unsigned lo = g_R0[w*1024 + t];
    const unsigned hi = g_R0[(w+1)*1024 + t];
    const unsigned m = (lo >> 1) | (hi << 31);
    Ms[r][w] = m;
    g_M[t*32 + w] = m;
  }
  __syncthreads();
  if(tid < 64){
    const int c = tid;
    const unsigned half = (c & 1) ? 0xFFFF0000u : 0x0000FFFFu;
    const int w = c >> 1;
    unsigned acc = 0u;
    #pragma unroll 8
    for(int r = 0; r < 64; r++) acc |= Ms[r][w];
    g_occ16[rt*64 + c] = (acc & half) ? 1 : 0;
    g_ksum[rt*64 + c] = 0.f;
    g_qsum[rt*64 + c] = 0.f;
  }
}

// ---------------- fused projections (tf32) + K/Q row-sum epilogue --------------
__global__ void proj_fused(const float* __restrict__ x,
                           const float* __restrict__ Wk, const float* __restrict__ Wq,
                           const float* __restrict__ Wv, const float* __restrict__ Ws,
                           const float* __restrict__ bskip){
  extern __shared__ float dsm[];
  const int z = blockIdx.z;
  const float* W = (z==0) ? Wk : (z==1) ? Wq : (z==2) ? Wv : Ws;
  float* C = (z==0) ? g_K : (z==1) ? g_Q : (z==2) ? g_V : g_SKIP;
  const int row0 = blockIdx.y*64, col0 = blockIdx.x*64;
  float acc[4][4] = {};
  tf32_tile<DD>(x, W, row0, col0, dsm, acc);
  const int lane = threadIdx.x & 31, wid = threadIdx.x >> 5;
  const int m0 = (wid & 3) * 16, n0 = (wid >> 2) * 32;
  const int r1 = row0 + m0 + (lane >> 2);
  float rs[2] = {0.f, 0.f};
  #pragma unroll
  for(int s = 0; s < 4; s++){
    const int c0 = col0 + n0 + s*8 + 2*(lane & 3);
    #pragma unroll
    for(int e = 0; e < 4; e++){
      const int row = r1 + (e >> 1)*8;
      const int col = c0 + (e & 1);
      float v = acc[s][e];
      if(z == 3) v += bskip[col];
      if(z < 2)  v = (v > 0.f) ? v : expm1f(v);
      rs[e >> 1] += v;
      C[row*HD + col] = v;
    }
  }
  if(z < 2){
    float* sum = (z == 0) ? g_ksum : g_qsum;
    #pragma unroll
    for(int o = 1; o <= 2; o <<= 1){
      rs[0] += __shfl_xor_sync(0xffffffffu, rs[0], o);
      rs[1] += __shfl_xor_sync(0xffffffffu, rs[1], o);
    }
    if((lane & 3) == 0){
      atomicAdd(&sum[r1],     rs[0]);
      atomicAdd(&sum[r1 + 8], rs[1]);
    }
  }
}

// ---------------- MLP GEMM (tf32): 64x64 tiles; buffers by id ----------------
__global__ void gemm_mlp(int a_id, const float* __restrict__ W,
                         const float* __restrict__ bias, int c_id,
                         int act, int add_skip){
  extern __shared__ float dsm[];
  const float* A = buf(a_id);
  float* C = buf(c_id);
  const int row0 = blockIdx.y*64, col0 = blockIdx.x*64;
  float acc[4][4] = {};
  tf32_tile<HD>(A, W, row0, col0, dsm, acc);
  const int lane = threadIdx.x & 31, wid = threadIdx.x >> 5;
  const int m0 = (wid & 3) * 16, n0 = (wid >> 2) * 32;
  const int r1 = row0 + m0 + (lane >> 2);
  #pragma unroll
  for(int s = 0; s < 4; s++){
    const int c0 = col0 + n0 + s*8 + 2*(lane & 3);
    #pragma unroll
    for(int e = 0; e < 4; e++){
      const int row = r1 + (e >> 1)*8;
      const int col = c0 + (e & 1);
      float v = acc[s][e] + bias[col];
      if(act == 2){
        const float sp = (v > 20.f) ? v : log1pf(expf(v));
        v = v * tanhf(sp);
      }
      if(add_skip) v += g_SKIP[row*HD + col];
      C[row*HD + col] = v;
    }
  }
}

// ---------------- masked QK^T (tf32) with exact tree mask ----------------
__global__ void qk_kernel(){
  extern __shared__ float dsm[];
  const int by = blockIdx.y, bx = blockIdx.x;
  if(bx > by) return;
  const unsigned occ4 = *(const unsigned*)&g_occ16[by*64 + bx*4];
  if(!occ4) return;
  const int r0 = by*64, c0 = bx*64;
  float acc[4][4] = {};
  tf32_tile<HD>(g_Q, g_K, r0, c0, dsm, acc);
  const int lane = threadIdx.x & 31, wid = threadIdx.x >> 5;
  const int m0 = (wid & 3) * 16, n0 = (wid >> 2) * 32;
  const int t1 = r0 + m0 + (lane >> 2);
  #pragma unroll
  for(int s = 0; s < 4; s++){
    const int u0 = c0 + n0 + s*8 + 2*(lane & 3);
    #pragma unroll
    for(int e = 0; e < 4; e++){
      const int t = t1 + (e >> 1)*8;
      const int u = u0 + (e & 1);
      const unsigned mw = g_M[t*32 + (u>>5)];
      g_S[t*TT + u] = ((mw >> (u&31)) & 1u) ? acc[s][e] : 0.f;
    }
  }
}

// ---------------- out = (S @ V) / den  (fp32, prefetched sparse chunks) --------
__global__ void sv_kernel(){
  const int by = blockIdx.y, bx = blockIdx.x;
  const int r0 = by*64, col0 = bx*64;
  __shared__ __align__(16) float As[16][68];
  __shared__ __align__(16) float Bs[16][64];
  __shared__ float den_s[64];
  __shared__ unsigned char occ_s[64];
  const int tid = threadIdx.x;
  const int lane = tid & 31, wid = tid >> 5;
  if(tid < 64) occ_s[tid] = g_occ16[by*64 + tid];
  // denom for this row-tile: 8 warps x 8 passes, lane-per-mask-word
  #pragma unroll
  for(int p = 0; p < 8; p++){
    const int row = r0 + p*8 + wid;
    unsigned m = g_M[row*32 + lane];
    float zz = 0.f;
    while(m){
      const int b = __ffs(m) - 1;
      zz += g_ksum[lane*32 + b];
      m &= m - 1;
    }
    #pragma unroll
    for(int o = 16; o; o >>= 1) zz += __shfl_down_sync(0xffffffffu, zz, o);
    if(lane == 0) den_s[p*8 + wid] = fmaxf(g_qsum[row] * zz, 1e-5f);
  }
  __syncthreads();

  const int tx = tid & 15, ty = tid >> 4;
  const int r  = tid >> 2, c4 = (tid & 3) << 2;
  const int vr = tid >> 4, vc4 = (tid & 15) << 2;
  const int maxc = by*4 + 3;
  float acc[4][4] = {};

  int cur = 0;
  while(cur <= maxc && !occ_s[cur]) cur++;
  if(cur <= maxc){
    float4 av = *(const float4*)&g_S[(r0 + r)*TT + cur*16 + c4];
    float4 bv = *(const float4*)&g_V[(cur*16 + vr)*HD + col0 + vc4];
    for(;;){
      int nxt = cur + 1;
      while(nxt <= maxc && !occ_s[nxt]) nxt++;
      As[c4+0][r]=av.x; As[c4+1][r]=av.y; As[c4+2][r]=av.z; As[c4+3][r]=av.w;
      *(float4*)&Bs[vr][vc4] = bv;
      __syncthreads();
      const bool more = (nxt <= maxc);
      if(more){
        av = *(const float4*)&g_S[(r0 + r)*TT + nxt*16 + c4];
        bv = *(const float4*)&g_V[(nxt*16 + vr)*HD + col0 + vc4];
      }
      #pragma unroll
      for(int k=0;k<16;k++){
        const float4 a4 = *(const float4*)&As[k][ty*4];
        const float4 b4 = *(const float4*)&Bs[k][tx*4];
        const float av2[4] = {a4.x,a4.y,a4.z,a4.w};
        #pragma unroll
        for(int i=0;i<4;i++){
          acc[i][0] += av2[i]*b4.x; acc[i][1] += av2[i]*b4.y;
          acc[i][2] += av2[i]*b4.z; acc[i][3] += av2[i]*b4.w;
        }
      }
      __syncthreads();
      if(!more) break;
      cur = nxt;
    }
  }
  #pragma unroll
  for(int i=0;i<4;i++){
    const int rr = ty*4 + i;
    const float inv = 1.f / den_s[rr];
    #pragma unroll
    for(int j=0;j<4;j++)
      g_ATT[(r0 + rr)*HD + col0 + tx*4 + j] = acc[i][j] * inv;
  }
}

// ---------------- LayerNorm over H=256 per row ----------------
__global__ void ln_kernel(const float* __restrict__ w, const float* __restrict__ b,
                          float* __restrict__ out){
  const int row = blockIdx.x, t = threadIdx.x;
  float v = g_H3[row*HD + t];
  __shared__ float red[8];
  __shared__ float sh_mu, sh_var;
  float s = v;
  #pragma unroll
  for(int o=16;o;o>>=1) s += __shfl_down_sync(0xffffffffu, s, o);
  if((t & 31) == 0) red[t >> 5] = s;
  __syncthreads();
  if(t == 0){ float tot = 0.f; for(int i=0;i<8;i++) tot += red[i]; sh_mu = tot / (float)HD; }
  __syncthreads();
  float d = v - sh_mu;
  float s2 = d*d;
  #pragma unroll
  for(int o=16;o;o>>=1) s2 += __shfl_down_sync(0xffffffffu, s2, o);
  if((t & 31) == 0) red[t >> 5] = s2;
  __syncthreads();
  if(t == 0){ float tot = 0.f; for(int i=0;i<8;i++) tot += red[i]; sh_var = tot / (float)HD; }
  __syncthreads();
  out[row*HD + t] = d * rsqrtf(sh_var + 1e-5f) * w[t] + b[t];
}

// ---------------- launch ----------------
extern "C" void kernel_launch(void* const* d_in, const int* in_sizes, int n_in,
                              void* d_out, int out_size){
  const float* x     = (const float*)d_in[0];
  const int*   start = (const int*)  d_in[3];
  const int*   done  = (const int*)  d_in[4];
  const float* Wk    = (const float*)d_in[5];
  const float* Wq    = (const float*)d_in[6];
  const float* Wv    = (const float*)d_in[7];
  const float* Wskip = (const float*)d_in[8];
  const float* bskip = (const float*)d_in[9];
  const float* W1    = (const float*)d_in[10];
  const float* b1    = (const float*)d_in[11];
  const float* W2    = (const float*)d_in[12];
  const float* b2    = (const float*)d_in[13];
  const float* W3    = (const float*)d_in[14];
  const float* b3    = (const float*)d_in[15];
  const float* lnw   = (const float*)d_in[16];
  const float* lnb   = (const float*)d_in[17];
  float* out = (float*)d_out;

  cudaFuncSetAttribute(proj_fused, cudaFuncAttributeMaxDynamicSharedMemorySize, SMEMB);
  cudaFuncSetAttribute(gemm_mlp,   cudaFuncAttributeMaxDynamicSharedMemorySize, SMEMB);
  cudaFuncSetAttribute(qk_kernel,  cudaFuncAttributeMaxDynamicSharedMemorySize, SMEMB);

  prep_scan<<<33, 256>>>(start, done);
  prep_mask<<<16, 512>>>();

  proj_fused<<<dim3(HD/64, TT/64, 4), 256, SMEMB>>>(x, Wk, Wq, Wv, Wskip, bskip);

  qk_kernel<<<dim3(TT/64, TT/64), 256, SMEMB>>>();
  sv_kernel<<<dim3(HD/64, TT/64), 256>>>();

  gemm_mlp<<<dim3(HD/64, TT/64), 256, SMEMB>>>(5, W1, b1, 6, 2, 0);   // ATT -> H1 (mish)
  gemm_mlp<<<dim3(HD/64, TT/64), 256, SMEMB>>>(6, W2, b2, 7, 2, 0);   // H1  -> H2 (mish)
  gemm_mlp<<<dim3(HD/64, TT/64), 256, SMEMB>>>(7, W3, b3, 8, 0, 1);   // H2  -> H3 (+skip)

  ln_kernel<<<TT, 256>>>(lnw, lnb, out);
}